// round 9
// baseline (speedup 1.0000x reference)
#include <cuda_runtime.h>
#include <math.h>

// Problem constants
#define BB 4
#define TT 512
#define DD 192
#define CHK 32
#define NC (TT/CHK)        // 16 chunks per batch
#define NBC (BB*NC)        // 64 chunk-blocks total
#define PAD 196            // smem row pitch (floats) for 192-wide tiles
#define VP  100            // smem pitch for 96-wide tiles

// ---------------- scratch (module-static device memory; no allocations) ----------------
__device__ float g_Q[BB*TT*DD];
__device__ float g_K[BB*TT*DD];
__device__ float g_V[BB*TT*DD];
__device__ float g_G  [(size_t)NBC*DD*DD];   // per-chunk K^T V   (9.4 MB)
__device__ float g_Sst[(size_t)NBC*DD*DD];   // exclusive prefix state (+S0)
__device__ float g_z  [(size_t)NBC*DD];      // per-chunk sum of K rows
__device__ float g_zst[(size_t)NBC*DD];      // exclusive prefix (+Z0)
__device__ float g_A  [(size_t)2*NBC*CHK*CHK]; // k-split partial scores

__device__ __forceinline__ float elu1(float v) {
    return v > 0.f ? v + 1.f : expf(v);
}

// ---- packed fp32x2 helpers (FFMA2) ----
__device__ __forceinline__ unsigned long long pack2(float lo, float hi) {
    unsigned long long r;
    asm("mov.b64 %0, {%1, %2};" : "=l"(r) : "f"(lo), "f"(hi));
    return r;
}
__device__ __forceinline__ void ffma2(unsigned long long& d,
                                      unsigned long long a, unsigned long long b) {
    asm("fma.rn.f32x2 %0, %1, %2, %0;" : "+l"(d) : "l"(a), "l"(b));
}
__device__ __forceinline__ void unpack2(unsigned long long v, float& lo, float& hi) {
    asm("mov.b64 {%0, %1}, %2;" : "=f"(lo), "=f"(hi) : "l"(v));
}

// ---------------- Kernel 1: qkv = x @ W^T + b, elu+1 on Q,K ---------------------------
__global__ __launch_bounds__(256) void qkv_kernel(const float* __restrict__ x,
                                                  const float* __restrict__ W,
                                                  const float* __restrict__ bias) {
    extern __shared__ float sm[];
    float* Xs = sm;                 // [64][PAD]
    float* Ws = sm + 64*PAD;        // [64][PAD]
    const int tid = threadIdx.x;
    const int m0 = blockIdx.x * 64;
    const int n0 = blockIdx.y * 64;

    for (int idx = tid; idx < 64*48; idx += 256) {
        int r = idx / 48, c4 = (idx % 48) * 4;
        *reinterpret_cast<float4*>(Xs + r*PAD + c4) =
            *reinterpret_cast<const float4*>(x + (size_t)(m0 + r)*DD + c4);
        *reinterpret_cast<float4*>(Ws + r*PAD + c4) =
            *reinterpret_cast<const float4*>(W + (size_t)(n0 + r)*DD + c4);
    }
    __syncthreads();

    const int tx = tid & 15;   // n lane
    const int ty = tid >> 4;   // m lane
    float acc[4][4];
    #pragma unroll
    for (int v = 0; v < 4; v++)
        #pragma unroll
        for (int u = 0; u < 4; u++) acc[v][u] = 0.f;

    for (int k = 0; k < DD; k++) {
        float a[4], w[4];
        #pragma unroll
        for (int v = 0; v < 4; v++) a[v] = Xs[(ty + 16*v)*PAD + k];
        #pragma unroll
        for (int u = 0; u < 4; u++) w[u] = Ws[(tx + 16*u)*PAD + k];
        #pragma unroll
        for (int v = 0; v < 4; v++)
            #pragma unroll
            for (int u = 0; u < 4; u++) acc[v][u] += a[v]*w[u];
    }

    #pragma unroll
    for (int v = 0; v < 4; v++) {
        int m = m0 + ty + 16*v;
        #pragma unroll
        for (int u = 0; u < 4; u++) {
            int n = n0 + tx + 16*u;
            float val = acc[v][u] + bias[n];
            if (n < DD)            g_Q[(size_t)m*DD + n]        = elu1(val);
            else if (n < 2*DD)     g_K[(size_t)m*DD + (n-DD)]   = elu1(val);
            else                   g_V[(size_t)m*DD + (n-2*DD)] = val;
        }
    }
}

// ---------------- Kernel 2: per-chunk G = K^T V (j-half per block) + z -----------------
// grid = 64 chunks x 2 j-halves. G[i][j] = sum_s K[s][i] * V[s][j], FFMA2 over j pairs.
__global__ __launch_bounds__(256) void chunk_kernel() {
    __shared__ float Ks[CHK*PAD];   // 32 x 192 (full i range)
    __shared__ float Vs[CHK*VP];    // 32 x 96  (this block's j-half)
    const int tid = threadIdx.x;
    const int bc = blockIdx.x >> 1;
    const int jh = blockIdx.x & 1;
    const int j0 = jh * 96;
    const int b = bc / NC, c = bc % NC;
    const size_t tbase = ((size_t)b*TT + (size_t)c*CHK) * DD;

    for (int idx = tid; idx < CHK*48; idx += 256) {
        int r = idx / 48, c4 = (idx % 48) * 4;
        *reinterpret_cast<float4*>(Ks + r*PAD + c4) =
            *reinterpret_cast<const float4*>(g_K + tbase + (size_t)r*DD + c4);
    }
    for (int idx = tid; idx < CHK*24; idx += 256) {
        int r = idx / 24, c4 = (idx % 24) * 4;
        *reinterpret_cast<float4*>(Vs + r*VP + c4) =
            *reinterpret_cast<const float4*>(g_V + tbase + (size_t)r*DD + j0 + c4);
    }
    __syncthreads();

    if (jh == 0 && tid < DD) {
        float zs = 0.f;
        #pragma unroll
        for (int s = 0; s < CHK; s++) zs += Ks[s*PAD + tid];
        g_z[(size_t)bc*DD + tid] = zs;
    }

    const int tx = tid & 15, ty = tid >> 4;
    unsigned long long acc2[12][3];
    #pragma unroll
    for (int a = 0; a < 12; a++)
        #pragma unroll
        for (int e = 0; e < 3; e++) acc2[a][e] = 0ull;

    #pragma unroll 4
    for (int s = 0; s < CHK; s++) {
        unsigned long long kd[12], vj[3];
        #pragma unroll
        for (int a = 0; a < 12; a++) {
            float kv = Ks[s*PAD + ty + 16*a];
            kd[a] = pack2(kv, kv);
        }
        #pragma unroll
        for (int e = 0; e < 3; e++)
            vj[e] = *reinterpret_cast<const unsigned long long*>(Vs + s*VP + 2*tx + 32*e);
        #pragma unroll
        for (int a = 0; a < 12; a++)
            #pragma unroll
            for (int e = 0; e < 3; e++) ffma2(acc2[a][e], kd[a], vj[e]);
    }

    float* Gp = g_G + (size_t)bc*(DD*DD);
    #pragma unroll
    for (int a = 0; a < 12; a++) {
        int i = ty + 16*a;
        #pragma unroll
        for (int e = 0; e < 3; e++) {
            float lo, hi; unpack2(acc2[a][e], lo, hi);
            *reinterpret_cast<float2*>(Gp + (size_t)i*DD + j0 + 2*tx + 32*e) =
                make_float2(lo, hi);
        }
    }
}

// ---------------- Kernel 2b: partial scores A = Q K^T, split over k halves --------------
// grid = 64 chunks x 2 k-halves. Stores UNMASKED partials; out_kernel sums + masks.
__global__ __launch_bounds__(256) void score_kernel() {
    __shared__ float Qk[CHK*VP];    // 32 x 96 (k-half)
    __shared__ float Kk[CHK*VP];
    const int tid = threadIdx.x;
    const int bc = blockIdx.x >> 1;
    const int kh = blockIdx.x & 1;
    const int k0 = kh * 96;
    const int b = bc / NC, c = bc % NC;
    const size_t tbase = ((size_t)b*TT + (size_t)c*CHK) * DD;

    for (int idx = tid; idx < CHK*24; idx += 256) {
        int r = idx / 24, c4 = (idx % 24) * 4;
        *reinterpret_cast<float4*>(Qk + r*VP + c4) =
            *reinterpret_cast<const float4*>(g_Q + tbase + (size_t)r*DD + k0 + c4);
        *reinterpret_cast<float4*>(Kk + r*VP + c4) =
            *reinterpret_cast<const float4*>(g_K + tbase + (size_t)r*DD + k0 + c4);
    }
    __syncthreads();

    const int tx = tid & 15, ty = tid >> 4;
    float acc[2][2] = {{0.f,0.f},{0.f,0.f}};
    for (int k = 0; k < 96; k++) {
        float q[2], kk[2];
        #pragma unroll
        for (int r = 0; r < 2; r++) q[r]  = Qk[(ty + 16*r)*VP + k];
        #pragma unroll
        for (int e = 0; e < 2; e++) kk[e] = Kk[(tx + 16*e)*VP + k];
        #pragma unroll
        for (int r = 0; r < 2; r++)
            #pragma unroll
            for (int e = 0; e < 2; e++) acc[r][e] += q[r]*kk[e];
    }

    float* Ap = g_A + ((size_t)kh*NBC + bc)*(CHK*CHK);
    #pragma unroll
    for (int r = 0; r < 2; r++)
        #pragma unroll
        for (int e = 0; e < 2; e++)
            Ap[(ty + 16*r)*CHK + tx + 16*e] = acc[r][e];
}

// ---------------- Kernel 3: fused exclusive prefix over chunks (S and z) ----------------
__global__ __launch_bounds__(256) void prefix_kernel(const float* __restrict__ S0,
                                                     const float* __restrict__ Z0,
                                                     float* __restrict__ outS,
                                                     float* __restrict__ outZ) {
    const int tid = threadIdx.x;
    if (blockIdx.x < 576) {
        int e = blockIdx.x * 256 + tid;              // e < B*D*D = 147456
        int b = e / (DD*DD), r = e - b*(DD*DD);
        size_t base = (size_t)b*NC*DD*DD + r;
        float v[NC];
        #pragma unroll
        for (int c = 0; c < NC; c++) v[c] = g_G[base + (size_t)c*DD*DD];
        float run = S0[e];
        #pragma unroll
        for (int c = 0; c < NC; c++) { float nv = run + v[c]; v[c] = run; run = nv; }
        #pragma unroll
        for (int c = 0; c < NC; c++) g_Sst[base + (size_t)c*DD*DD] = v[c];
        outS[e] = run;   // S[:, -1]  (clip @1e20 never binds)
    } else {
        int e = (blockIdx.x - 576) * 256 + tid;
        if (e >= BB*DD) return;
        int b = e / DD, i = e - b*DD;
        size_t base = (size_t)b*NC*DD + i;
        float v[NC];
        #pragma unroll
        for (int c = 0; c < NC; c++) v[c] = g_z[base + (size_t)c*DD];
        float run = Z0[e];
        #pragma unroll
        for (int c = 0; c < NC; c++) { float nv = run + v[c]; v[c] = run; run = nv; }
        #pragma unroll
        for (int c = 0; c < NC; c++) g_zst[base + (size_t)c*DD] = v[c];
        outZ[e] = run;
    }
}

// ---------------- Kernel 4: per-chunk output (j-half per block) -------------------------
// out[t] = (Q[t].S_start + (masked A) V) / (Q[t].z_start + rowsum(masked A) + 1e-5)
__global__ __launch_bounds__(256) void out_kernel(float* __restrict__ out) {
    extern __shared__ float sm[];
    float* Qs   = sm;                   // [32][PAD]
    float* Vs   = Qs + CHK*PAD;         // [32][VP]  (j-half)
    float* As   = Vs + CHK*VP;          // [32][33]  masked scores
    float* dens = As + CHK*33;          // [32]
    float* Pan  = dens + 32;            // 2 x [32][96]  S-panel double buffer

    const int tid = threadIdx.x;
    const int bc = blockIdx.x >> 1;
    const int jh = blockIdx.x & 1;
    const int j0 = jh * 96;
    const int b = bc / NC, c = bc % NC;
    const size_t tbase = ((size_t)b*TT + (size_t)c*CHK) * DD;

    for (int idx = tid; idx < CHK*48; idx += 256) {
        int r = idx / 48, c4 = (idx % 48) * 4;
        *reinterpret_cast<float4*>(Qs + r*PAD + c4) =
            *reinterpret_cast<const float4*>(g_Q + tbase + (size_t)r*DD + c4);
    }
    for (int idx = tid; idx < CHK*24; idx += 256) {
        int r = idx / 24, c4 = (idx % 24) * 4;
        *reinterpret_cast<float4*>(Vs + r*VP + c4) =
            *reinterpret_cast<const float4*>(g_V + tbase + (size_t)r*DD + j0 + c4);
    }
    // scores: sum k-split partials, apply causal mask
    {
        const float* A0 = g_A + (size_t)bc*(CHK*CHK);
        const float* A1 = g_A + ((size_t)NBC + bc)*(CHK*CHK);
        for (int idx = tid; idx < CHK*CHK; idx += 256) {
            int t_ = idx >> 5, s_ = idx & 31;
            float a = A0[idx] + A1[idx];
            As[t_*33 + s_] = (s_ <= t_) ? a : 0.f;
        }
    }
    __syncthreads();

    // denominators: Q.z_start + rowsum(masked A)
    if (tid < CHK) {
        const float* zp = g_zst + (size_t)bc*DD;
        float ds = 0.f;
        for (int k = 0; k < DD; k++) ds += Qs[tid*PAD + k] * zp[k];
        #pragma unroll
        for (int s = 0; s < CHK; s++) ds += As[tid*33 + s];
        dens[tid] = ds + 1e-5f;
    }

    const int tjp = tid & 15;    // j pair base: j = 2*tjp + 32u, u<3
    const int tt  = tid >> 4;    // t rows {2tt, 2tt+1}
    unsigned long long acc2[2][3];
    #pragma unroll
    for (int r = 0; r < 2; r++)
        #pragma unroll
        for (int u = 0; u < 3; u++) acc2[r][u] = 0ull;

    // intra-chunk: masked A @ V
    #pragma unroll 4
    for (int s = 0; s < CHK; s++) {
        unsigned long long ad[2], vv[3];
        #pragma unroll
        for (int r = 0; r < 2; r++) {
            float a = As[(2*tt + r)*33 + s];
            ad[r] = pack2(a, a);
        }
        #pragma unroll
        for (int u = 0; u < 3; u++)
            vv[u] = *reinterpret_cast<const unsigned long long*>(Vs + s*VP + 2*tjp + 32*u);
        #pragma unroll
        for (int r = 0; r < 2; r++)
            #pragma unroll
            for (int u = 0; u < 3; u++) ffma2(acc2[r][u], ad[r], vv[u]);
    }

    // inter-chunk: Q @ S_start, 6 panels of 32 i-rows, register double-buffered
    const float* Sp = g_Sst + (size_t)bc*(DD*DD);
    float4 rg[3];
    #pragma unroll
    for (int q = 0; q < 3; q++) {
        int fi = tid + 256*q, r = fi / 24, c4 = (fi % 24) * 4;
        rg[q] = *reinterpret_cast<const float4*>(Sp + (size_t)r*DD + j0 + c4);
    }

    for (int p = 0; p < 6; p++) {
        float* buf = Pan + (p & 1) * (32*96);
        __syncthreads();
        #pragma unroll
        for (int q = 0; q < 3; q++) {
            int fi = tid + 256*q, r = fi / 24, c4 = (fi % 24) * 4;
            *reinterpret_cast<float4*>(buf + r*96 + c4) = rg[q];
        }
        if (p < 5) {
            #pragma unroll
            for (int q = 0; q < 3; q++) {
                int fi = tid + 256*q, r = fi / 24, c4 = (fi % 24) * 4;
                rg[q] = *reinterpret_cast<const float4*>(
                    Sp + (size_t)(32*(p+1) + r)*DD + j0 + c4);
            }
        }
        __syncthreads();
        #pragma unroll 4
        for (int i = 0; i < 32; i++) {
            unsigned long long qd[2], sv[3];
            #pragma unroll
            for (int r = 0; r < 2; r++) {
                float q = Qs[(2*tt + r)*PAD + 32*p + i];
                qd[r] = pack2(q, q);
            }
            #pragma unroll
            for (int u = 0; u < 3; u++)
                sv[u] = *reinterpret_cast<const unsigned long long*>(buf + i*96 + 2*tjp + 32*u);
            #pragma unroll
            for (int r = 0; r < 2; r++)
                #pragma unroll
                for (int u = 0; u < 3; u++) ffma2(acc2[r][u], qd[r], sv[u]);
        }
    }

    #pragma unroll
    for (int r = 0; r < 2; r++) {
        int t = 2*tt + r;
        float dv = dens[t];
        #pragma unroll
        for (int u = 0; u < 3; u++) {
            float lo, hi; unpack2(acc2[r][u], lo, hi);
            *reinterpret_cast<float2*>(out + tbase + (size_t)t*DD + j0 + 2*tjp + 32*u) =
                make_float2(lo / dv, hi / dv);
        }
    }
}

// ---------------- launch ----------------------------------------------------------------
extern "C" void kernel_launch(void* const* d_in, const int* in_sizes, int n_in,
                              void* d_out, int out_size) {
    const float* x  = (const float*)d_in[0];
    const float* W  = (const float*)d_in[1];
    const float* bi = (const float*)d_in[2];
    const float* S0 = (const float*)d_in[3];
    const float* Z0 = (const float*)d_in[4];
    float* out = (float*)d_out;

    const int SM1 = 2*64*PAD*4;                                   // 100352 B
    const int SM4 = (CHK*PAD + CHK*VP + CHK*33 + 32 + 2*32*96)*4; // ~67 KB
    cudaFuncSetAttribute(qkv_kernel, cudaFuncAttributeMaxDynamicSharedMemorySize, SM1);
    cudaFuncSetAttribute(out_kernel, cudaFuncAttributeMaxDynamicSharedMemorySize, SM4);

    qkv_kernel<<<dim3(32, 9), 256, SM1>>>(x, W, bi);
    chunk_kernel<<<2*NBC, 256>>>();
    score_kernel<<<2*NBC, 256>>>();
    prefix_kernel<<<579, 256>>>(S0, Z0,
                                out + (size_t)BB*TT*DD,
                                out + (size_t)BB*TT*DD + (size_t)BB*DD*DD);
    out_kernel<<<2*NBC, 256, SM4>>>(out);
}

// round 11
// speedup vs baseline: 1.0351x; 1.0351x over previous
#include <cuda_runtime.h>
#include <math.h>

// Problem constants
#define BB 4
#define TT 512
#define DD 192
#define CHK 32
#define NC (TT/CHK)        // 16 chunks per batch
#define NBC (BB*NC)        // 64 chunk-blocks total
#define PAD 196            // smem row pitch (floats) for 192-wide tiles
#define VP  100            // smem pitch for 96-wide tiles
#define WXP 130            // Xt pitch (128 m + 2 pad)

// ---------------- scratch (module-static device memory; no allocations) ----------------
__device__ float g_Q[BB*TT*DD];
__device__ float g_K[BB*TT*DD];
__device__ float g_V[BB*TT*DD];
__device__ float g_G  [(size_t)NBC*DD*DD];   // per-chunk K^T V   (9.4 MB)
__device__ float g_Sst[(size_t)NBC*DD*DD];   // exclusive prefix state (+S0)
__device__ float g_z  [(size_t)NBC*DD];      // per-chunk sum of K rows
__device__ float g_zst[(size_t)NBC*DD];      // exclusive prefix (+Z0)
__device__ float g_A  [(size_t)2*NBC*CHK*CHK]; // k-split partial scores

__device__ __forceinline__ float elu1(float v) {
    return v > 0.f ? v + 1.f : expf(v);
}

// ---- packed fp32x2 helpers (FFMA2) ----
__device__ __forceinline__ unsigned long long pack2(float lo, float hi) {
    unsigned long long r;
    asm("mov.b64 %0, {%1, %2};" : "=l"(r) : "f"(lo), "f"(hi));
    return r;
}
__device__ __forceinline__ void ffma2(unsigned long long& d,
                                      unsigned long long a, unsigned long long b) {
    asm("fma.rn.f32x2 %0, %1, %2, %0;" : "+l"(d) : "l"(a), "l"(b));
}
__device__ __forceinline__ void unpack2(unsigned long long v, float& lo, float& hi) {
    asm("mov.b64 {%0, %1}, %2;" : "=f"(lo), "=f"(hi) : "l"(v));
}

// ---------------- Kernel 1: qkv = x @ W^T + b, elu+1 on Q,K (FFMA2, m-paired) ----------
// M=2048, N=576, K=192. 128x64 block tile, 256 threads, 8m x 4n microtile.
// grid = 16 x 9 = 144 blocks = one full wave.
__global__ __launch_bounds__(256) void qkv_kernel(const float* __restrict__ x,
                                                  const float* __restrict__ W,
                                                  const float* __restrict__ bias) {
    extern __shared__ float sm[];
    float* Xt = sm;              // [192][WXP]  k-major, m contiguous (for LDS.64 m-pairs)
    float* Ws = sm + DD*WXP;     // [64][PAD]   n-major, k contiguous
    const int tid = threadIdx.x;
    const int m0 = blockIdx.x * 128;
    const int n0 = blockIdx.y * 64;

    // load X transposed into Xt[k][m]
    for (int idx = tid; idx < 128*48; idx += 256) {
        int r = idx / 48, c4 = (idx % 48) * 4;
        float4 xv = *reinterpret_cast<const float4*>(x + (size_t)(m0 + r)*DD + c4);
        Xt[(c4+0)*WXP + r] = xv.x;
        Xt[(c4+1)*WXP + r] = xv.y;
        Xt[(c4+2)*WXP + r] = xv.z;
        Xt[(c4+3)*WXP + r] = xv.w;
    }
    // load W rows (n-major)
    for (int idx = tid; idx < 64*48; idx += 256) {
        int r = idx / 48, c4 = (idx % 48) * 4;
        *reinterpret_cast<float4*>(Ws + r*PAD + c4) =
            *reinterpret_cast<const float4*>(W + (size_t)(n0 + r)*DD + c4);
    }
    __syncthreads();

    const int tm = tid & 15;   // m pair lane: m = 2*tm + 32*v
    const int ty = tid >> 4;   // n lane:      n = ty + 16*u
    unsigned long long acc2[4][4];
    #pragma unroll
    for (int v = 0; v < 4; v++)
        #pragma unroll
        for (int u = 0; u < 4; u++) acc2[v][u] = 0ull;

    for (int k = 0; k < DD; k++) {
        unsigned long long a[4];
        #pragma unroll
        for (int v = 0; v < 4; v++)
            a[v] = *reinterpret_cast<const unsigned long long*>(Xt + k*WXP + 2*tm + 32*v);
        #pragma unroll
        for (int u = 0; u < 4; u++) {
            float wv = Ws[(ty + 16*u)*PAD + k];
            unsigned long long wd = pack2(wv, wv);
            #pragma unroll
            for (int v = 0; v < 4; v++) ffma2(acc2[v][u], a[v], wd);
        }
    }

    #pragma unroll
    for (int u = 0; u < 4; u++) {
        int n = n0 + ty + 16*u;
        float bv = bias[n];
        #pragma unroll
        for (int v = 0; v < 4; v++) {
            float lo, hi; unpack2(acc2[v][u], lo, hi);
            int m = m0 + 2*tm + 32*v;
            float v0 = lo + bv, v1 = hi + bv;
            if (n < DD) {
                g_Q[(size_t)m*DD + n]     = elu1(v0);
                g_Q[(size_t)(m+1)*DD + n] = elu1(v1);
            } else if (n < 2*DD) {
                g_K[(size_t)m*DD + (n-DD)]     = elu1(v0);
                g_K[(size_t)(m+1)*DD + (n-DD)] = elu1(v1);
            } else {
                g_V[(size_t)m*DD + (n-2*DD)]     = v0;
                g_V[(size_t)(m+1)*DD + (n-2*DD)] = v1;
            }
        }
    }
}

// ---------------- Kernel 2: per-chunk G = K^T V (j-half) + z + A partial (k-half) ------
// grid = 64 chunks x 2 halves. jh doubles as the k-half index for the score partial.
__global__ __launch_bounds__(256) void chunkscore_kernel() {
    extern __shared__ float sm[];
    float* Ks = sm;               // [32][PAD]  full i range of K
    float* Vs = Ks + CHK*PAD;     // [32][VP]   this block's j-half of V
    float* Qk = Vs + CHK*VP;      // [32][VP]   this block's k-half of Q
    const int tid = threadIdx.x;
    const int bc = blockIdx.x >> 1;
    const int jh = blockIdx.x & 1;
    const int j0 = jh * 96;
    const int b = bc / NC, c = bc % NC;
    const size_t tbase = ((size_t)b*TT + (size_t)c*CHK) * DD;

    for (int idx = tid; idx < CHK*48; idx += 256) {
        int r = idx / 48, c4 = (idx % 48) * 4;
        *reinterpret_cast<float4*>(Ks + r*PAD + c4) =
            *reinterpret_cast<const float4*>(g_K + tbase + (size_t)r*DD + c4);
    }
    for (int idx = tid; idx < CHK*24; idx += 256) {
        int r = idx / 24, c4 = (idx % 24) * 4;
        *reinterpret_cast<float4*>(Vs + r*VP + c4) =
            *reinterpret_cast<const float4*>(g_V + tbase + (size_t)r*DD + j0 + c4);
        *reinterpret_cast<float4*>(Qk + r*VP + c4) =
            *reinterpret_cast<const float4*>(g_Q + tbase + (size_t)r*DD + j0 + c4);
    }
    __syncthreads();

    if (jh == 0 && tid < DD) {
        float zs = 0.f;
        #pragma unroll
        for (int s = 0; s < CHK; s++) zs += Ks[s*PAD + tid];
        g_z[(size_t)bc*DD + tid] = zs;
    }

    const int tx = tid & 15, ty = tid >> 4;

    // A partial for k-half jh: A[t][s] = sum_{k in half} Q[t][k] * K[s][k]
    {
        float a2[2][2] = {{0.f,0.f},{0.f,0.f}};
        for (int k = 0; k < 96; k++) {
            float q[2], kk[2];
            #pragma unroll
            for (int r = 0; r < 2; r++) q[r]  = Qk[(ty + 16*r)*VP + k];
            #pragma unroll
            for (int e = 0; e < 2; e++) kk[e] = Ks[(tx + 16*e)*PAD + j0 + k];
            #pragma unroll
            for (int r = 0; r < 2; r++)
                #pragma unroll
                for (int e = 0; e < 2; e++) a2[r][e] += q[r]*kk[e];
        }
        float* Ap = g_A + ((size_t)jh*NBC + bc)*(CHK*CHK);
        #pragma unroll
        for (int r = 0; r < 2; r++)
            #pragma unroll
            for (int e = 0; e < 2; e++)
                Ap[(ty + 16*r)*CHK + tx + 16*e] = a2[r][e];
    }

    // G = K^T V for this j-half (FFMA2 over j pairs)
    unsigned long long acc2[12][3];
    #pragma unroll
    for (int a = 0; a < 12; a++)
        #pragma unroll
        for (int e = 0; e < 3; e++) acc2[a][e] = 0ull;

    #pragma unroll 4
    for (int s = 0; s < CHK; s++) {
        unsigned long long kd[12], vj[3];
        #pragma unroll
        for (int a = 0; a < 12; a++) {
            float kv = Ks[s*PAD + ty + 16*a];
            kd[a] = pack2(kv, kv);
        }
        #pragma unroll
        for (int e = 0; e < 3; e++)
            vj[e] = *reinterpret_cast<const unsigned long long*>(Vs + s*VP + 2*tx + 32*e);
        #pragma unroll
        for (int a = 0; a < 12; a++)
            #pragma unroll
            for (int e = 0; e < 3; e++) ffma2(acc2[a][e], kd[a], vj[e]);
    }

    float* Gp = g_G + (size_t)bc*(DD*DD);
    #pragma unroll
    for (int a = 0; a < 12; a++) {
        int i = ty + 16*a;
        #pragma unroll
        for (int e = 0; e < 3; e++) {
            float lo, hi; unpack2(acc2[a][e], lo, hi);
            *reinterpret_cast<float2*>(Gp + (size_t)i*DD + j0 + 2*tx + 32*e) =
                make_float2(lo, hi);
        }
    }
}

// ---------------- Kernel 3: fused exclusive prefix (S and z), float4 lanes -------------
// Blocks [0,144): S path, one thread per 4 consecutive state elements (16 LDG.128, MLP=16).
// Block 144: z path.
__global__ __launch_bounds__(256) void prefix_kernel(const float* __restrict__ S0,
                                                     const float* __restrict__ Z0,
                                                     float* __restrict__ outS,
                                                     float* __restrict__ outZ) {
    const int tid = threadIdx.x;
    if (blockIdx.x < 144) {
        int e4 = blockIdx.x * 256 + tid;             // < B*D*D/4 = 36864
        int b = e4 / (DD*DD/4), r4 = e4 - b*(DD*DD/4);
        const float* Gp = g_G + (size_t)b*NC*DD*DD + (size_t)r4*4;
        float*       Sp = g_Sst + (size_t)b*NC*DD*DD + (size_t)r4*4;
        float4 v[NC];
        #pragma unroll
        for (int c = 0; c < NC; c++)
            v[c] = *reinterpret_cast<const float4*>(Gp + (size_t)c*DD*DD);
        float4 run = *reinterpret_cast<const float4*>(S0 + (size_t)e4*4);
        #pragma unroll
        for (int c = 0; c < NC; c++) {
            float4 nv = make_float4(run.x + v[c].x, run.y + v[c].y,
                                    run.z + v[c].z, run.w + v[c].w);
            v[c] = run; run = nv;
        }
        #pragma unroll
        for (int c = 0; c < NC; c++)
            *reinterpret_cast<float4*>(Sp + (size_t)c*DD*DD) = v[c];
        *reinterpret_cast<float4*>(outS + (size_t)e4*4) = run;  // S[:, -1]
    } else {
        int e4 = tid;                                 // < B*D/4 = 192
        if (e4 >= BB*DD/4) return;
        int b = e4 / (DD/4), i4 = e4 - b*(DD/4);
        const float* zp = g_z  + (size_t)b*NC*DD + (size_t)i4*4;
        float*      zsp = g_zst + (size_t)b*NC*DD + (size_t)i4*4;
        float4 v[NC];
        #pragma unroll
        for (int c = 0; c < NC; c++)
            v[c] = *reinterpret_cast<const float4*>(zp + (size_t)c*DD);
        float4 run = *reinterpret_cast<const float4*>(Z0 + (size_t)e4*4);
        #pragma unroll
        for (int c = 0; c < NC; c++) {
            float4 nv = make_float4(run.x + v[c].x, run.y + v[c].y,
                                    run.z + v[c].z, run.w + v[c].w);
            v[c] = run; run = nv;
        }
        #pragma unroll
        for (int c = 0; c < NC; c++)
            *reinterpret_cast<float4*>(zsp + (size_t)c*DD) = v[c];
        *reinterpret_cast<float4*>(outZ + (size_t)e4*4) = run;
    }
}

// ---------------- Kernel 4: per-chunk output (j-half per block) -------------------------
__global__ __launch_bounds__(256) void out_kernel(float* __restrict__ out) {
    extern __shared__ float sm[];
    float* Qs   = sm;                   // [32][PAD]
    float* Vs   = Qs + CHK*PAD;         // [32][VP]  (j-half)
    float* As   = Vs + CHK*VP;          // [32][33]  masked scores
    float* dens = As + CHK*33;          // [32]
    float* Pan  = dens + 32;            // 2 x [32][96]  S-panel double buffer

    const int tid = threadIdx.x;
    const int bc = blockIdx.x >> 1;
    const int jh = blockIdx.x & 1;
    const int j0 = jh * 96;
    const int b = bc / NC, c = bc % NC;
    const size_t tbase = ((size_t)b*TT + (size_t)c*CHK) * DD;

    for (int idx = tid; idx < CHK*48; idx += 256) {
        int r = idx / 48, c4 = (idx % 48) * 4;
        *reinterpret_cast<float4*>(Qs + r*PAD + c4) =
            *reinterpret_cast<const float4*>(g_Q + tbase + (size_t)r*DD + c4);
    }
    for (int idx = tid; idx < CHK*24; idx += 256) {
        int r = idx / 24, c4 = (idx % 24) * 4;
        *reinterpret_cast<float4*>(Vs + r*VP + c4) =
            *reinterpret_cast<const float4*>(g_V + tbase + (size_t)r*DD + j0 + c4);
    }
    // scores: sum k-split partials, apply causal mask
    {
        const float* A0 = g_A + (size_t)bc*(CHK*CHK);
        const float* A1 = g_A + ((size_t)NBC + bc)*(CHK*CHK);
        for (int idx = tid; idx < CHK*CHK; idx += 256) {
            int t_ = idx >> 5, s_ = idx & 31;
            float a = A0[idx] + A1[idx];
            As[t_*33 + s_] = (s_ <= t_) ? a : 0.f;
        }
    }
    __syncthreads();

    // denominators: Q.z_start + rowsum(masked A)
    if (tid < CHK) {
        const float* zp = g_zst + (size_t)bc*DD;
        float ds = 0.f;
        for (int k = 0; k < DD; k++) ds += Qs[tid*PAD + k] * zp[k];
        #pragma unroll
        for (int s = 0; s < CHK; s++) ds += As[tid*33 + s];
        dens[tid] = ds + 1e-5f;
    }

    const int tjp = tid & 15;    // j pair base: j = 2*tjp + 32u, u<3
    const int tt  = tid >> 4;    // t rows {2tt, 2tt+1}
    unsigned long long acc2[2][3];
    #pragma unroll
    for (int r = 0; r < 2; r++)
        #pragma unroll
        for (int u = 0; u < 3; u++) acc2[r][u] = 0ull;

    // intra-chunk: masked A @ V
    #pragma unroll 4
    for (int s = 0; s < CHK; s++) {
        unsigned long long ad[2], vv[3];
        #pragma unroll
        for (int r = 0; r < 2; r++) {
            float a = As[(2*tt + r)*33 + s];
            ad[r] = pack2(a, a);
        }
        #pragma unroll
        for (int u = 0; u < 3; u++)
            vv[u] = *reinterpret_cast<const unsigned long long*>(Vs + s*VP + 2*tjp + 32*u);
        #pragma unroll
        for (int r = 0; r < 2; r++)
            #pragma unroll
            for (int u = 0; u < 3; u++) ffma2(acc2[r][u], ad[r], vv[u]);
    }

    // inter-chunk: Q @ S_start, 6 panels of 32 i-rows, register double-buffered
    const float* Sp = g_Sst + (size_t)bc*(DD*DD);
    float4 rg[3];
    #pragma unroll
    for (int q = 0; q < 3; q++) {
        int fi = tid + 256*q, r = fi / 24, c4 = (fi % 24) * 4;
        rg[q] = *reinterpret_cast<const float4*>(Sp + (size_t)r*DD + j0 + c4);
    }

    for (int p = 0; p < 6; p++) {
        float* buf = Pan + (p & 1) * (32*96);
        __syncthreads();
        #pragma unroll
        for (int q = 0; q < 3; q++) {
            int fi = tid + 256*q, r = fi / 24, c4 = (fi % 24) * 4;
            *reinterpret_cast<float4*>(buf + r*96 + c4) = rg[q];
        }
        if (p < 5) {
            #pragma unroll
            for (int q = 0; q < 3; q++) {
                int fi = tid + 256*q, r = fi / 24, c4 = (fi % 24) * 4;
                rg[q] = *reinterpret_cast<const float4*>(
                    Sp + (size_t)(32*(p+1) + r)*DD + j0 + c4);
            }
        }
        __syncthreads();
        #pragma unroll 4
        for (int i = 0; i < 32; i++) {
            unsigned long long qd[2], sv[3];
            #pragma unroll
            for (int r = 0; r < 2; r++) {
                float q = Qs[(2*tt + r)*PAD + 32*p + i];
                qd[r] = pack2(q, q);
            }
            #pragma unroll
            for (int u = 0; u < 3; u++)
                sv[u] = *reinterpret_cast<const unsigned long long*>(buf + i*96 + 2*tjp + 32*u);
            #pragma unroll
            for (int r = 0; r < 2; r++)
                #pragma unroll
                for (int u = 0; u < 3; u++) ffma2(acc2[r][u], qd[r], sv[u]);
        }
    }

    #pragma unroll
    for (int r = 0; r < 2; r++) {
        int t = 2*tt + r;
        float dv = dens[t];
        #pragma unroll
        for (int u = 0; u < 3; u++) {
            float lo, hi; unpack2(acc2[r][u], lo, hi);
            *reinterpret_cast<float2*>(out + tbase + (size_t)t*DD + j0 + 2*tjp + 32*u) =
                make_float2(lo / dv, hi / dv);
        }
    }
}

// ---------------- launch ----------------------------------------------------------------
extern "C" void kernel_launch(void* const* d_in, const int* in_sizes, int n_in,
                              void* d_out, int out_size) {
    const float* x  = (const float*)d_in[0];
    const float* W  = (const float*)d_in[1];
    const float* bi = (const float*)d_in[2];
    const float* S0 = (const float*)d_in[3];
    const float* Z0 = (const float*)d_in[4];
    float* out = (float*)d_out;

    const int SM1 = (DD*WXP + 64*PAD)*4;                          // 150016 B
    const int SM2 = (CHK*PAD + 2*CHK*VP)*4;                       // 50688 B
    const int SM4 = (CHK*PAD + CHK*VP + CHK*33 + 32 + 2*32*96)*4; // ~67 KB
    cudaFuncSetAttribute(qkv_kernel, cudaFuncAttributeMaxDynamicSharedMemorySize, SM1);
    cudaFuncSetAttribute(chunkscore_kernel, cudaFuncAttributeMaxDynamicSharedMemorySize, SM2);
    cudaFuncSetAttribute(out_kernel, cudaFuncAttributeMaxDynamicSharedMemorySize, SM4);

    qkv_kernel<<<dim3(16, 9), 256, SM1>>>(x, W, bi);
    chunkscore_kernel<<<2*NBC, 256, SM2>>>();
    prefix_kernel<<<145, 256>>>(S0, Z0,
                                out + (size_t)BB*TT*DD,
                                out + (size_t)BB*TT*DD + (size_t)BB*DD*DD);
    out_kernel<<<2*NBC, 256, SM4>>>(out);
}